// round 11
// baseline (speedup 1.0000x reference)
#include <cuda_runtime.h>
#include <cuda_fp16.h>
#include <math.h>

#define N_CAPS 64
#define IN_CAPS 4096
#define CAP_DIM 32
#define IN_DIM 16
#define EPS 1e-7f

#define RGRID 128                // routing blocks; co-resident (1 block/SM)
#define RTPB 1024
#define NWARP 32
#define PPB (N_CAPS * IN_CAPS / RGRID)  // 2048 pairs per routing block
#define PPW (PPB / NWARP)               // 64 pairs per warp

// globals (allocation-free rule)
__device__ __half g_u16[(size_t)N_CAPS * IN_CAPS * CAP_DIM];  // 16.75 MB fp16 u
__device__ float g_ps[RGRID][CAP_DIM];    // per-block partial S
__device__ float g_pz[RGRID];             // per-block partial Z
__device__ float g_v[N_CAPS * CAP_DIM];   // cumulative v
__device__ unsigned int g_cnt[3] = {0u, 0u, 0u};
__device__ unsigned int g_flag[2] = {0u, 0u};

// ---------------------------------------------------------------------------
// u[n,i,d] = sum_k W[n,i,d,k] * x[i,k]
// EXACT config that measured >=7.2 TB/s standalone (R3/R4): one warp per
// (n,i) pair, lane = d, 256 tpb, huge grid, no smem, compiler-scheduled.
// Output now fp16 (word k of pair = dims 2k,2k+1 — the routing layout).
// ---------------------------------------------------------------------------
__global__ __launch_bounds__(256) void uhat_kernel(const float* __restrict__ W,
                                                   const float* __restrict__ x) {
    int w = blockIdx.x * 8 + (threadIdx.x >> 5);   // global pair index
    int lane = threadIdx.x & 31;                   // d
    int i = w & (IN_CAPS - 1);

    const float4* xp = reinterpret_cast<const float4*>(x + (size_t)i * IN_DIM);
    float4 x0 = xp[0], x1 = xp[1], x2 = xp[2], x3 = xp[3];  // warp-uniform bcast

    const float4* wp = reinterpret_cast<const float4*>(
        W + ((size_t)w * CAP_DIM + lane) * IN_DIM);
    float4 w0 = wp[0], w1 = wp[1], w2 = wp[2], w3 = wp[3];

    float acc = w0.x * x0.x + w0.y * x0.y + w0.z * x0.z + w0.w * x0.w;
    acc      += w1.x * x1.x + w1.y * x1.y + w1.z * x1.z + w1.w * x1.w;
    acc      += w2.x * x2.x + w2.y * x2.y + w2.z * x2.z + w2.w * x2.w;
    acc      += w3.x * x3.x + w3.y * x3.y + w3.z * x3.z + w3.w * x3.w;

    g_u16[(size_t)w * CAP_DIM + lane] = __float2half_rn(acc);
}

// ---------------------------------------------------------------------------
// Persistent routing kernel: 3 iterations over u (L2-resident, 16.75 MB),
// software grid barrier + last-block combine each iteration.
// Block blk owns pairs [blk*PPB, (blk+1)*PPB); n = blk>>1.
// 16-lane groups: lane k owns dims 2k,2k+1; 64 groups stride the block's pairs.
// ---------------------------------------------------------------------------
__global__ void __launch_bounds__(RTPB, 1)
route_kernel(float* __restrict__ out)
{
    const int tid  = threadIdx.x;
    const int wid  = tid >> 5;
    const int lane = tid & 31;
    const int blk  = blockIdx.x;
    const int n    = blk >> 1;

    const unsigned int* __restrict__ u32 =
        reinterpret_cast<const unsigned int*>(g_u16) + (size_t)blk * PPB * 16;

    __shared__ float2 sm_B[NWARP][CAP_DIM];
    __shared__ float  sm_z[NWARP];
    __shared__ float  sm_red[NWARP];
    __shared__ float  sm_scale;
    __shared__ unsigned int sm_last;

    for (int t = 0; t < 3; t++) {
        // ---- scan: partial S (and Z for t>0) over this block's pairs ----
        {
            const int l16 = lane & 15;
            float2 vv = make_float2(0.f, 0.f);
            if (t > 0)
                vv = *reinterpret_cast<const float2*>(&g_v[n * CAP_DIM + 2 * l16]);
            float ax = 0.f, ay = 0.f, z = 0.f;
            const int pbase = wid * PPW + (lane >> 4);
#pragma unroll 4
            for (int s2 = 0; s2 < PPW / 2; s2++) {
                unsigned int wrd = u32[(pbase + 2 * s2) * 16 + l16];
                __half2 h = *reinterpret_cast<__half2*>(&wrd);
                float2 uu = __half22float2(h);
                float e;
                if (t > 0) {
                    float dt = uu.x * vv.x + uu.y * vv.y;
                    dt += __shfl_xor_sync(0xffffffffu, dt, 1);
                    dt += __shfl_xor_sync(0xffffffffu, dt, 2);
                    dt += __shfl_xor_sync(0xffffffffu, dt, 4);
                    dt += __shfl_xor_sync(0xffffffffu, dt, 8);   // 16-lane dot
                    e = __expf(dt);
                } else {
                    e = 1.0f;          // logits are zero on iter 0
                }
                ax += e * uu.x; ay += e * uu.y; z += e;
            }
            sm_B[wid][lane] = make_float2(ax, ay);
#pragma unroll
            for (int o = 16; o > 0; o >>= 1) z += __shfl_xor_sync(0xffffffffu, z, o);
            if (lane == 0) sm_z[wid] = z;
            __syncthreads();
            if (tid < CAP_DIM) {
                const int k = tid >> 1, j = tid & 1;
                float s = 0.f;
#pragma unroll
                for (int w2 = 0; w2 < NWARP; w2++) {
                    float2 a  = sm_B[w2][k];
                    float2 b2 = sm_B[w2][k + 16];
                    s += j ? (a.y + b2.y) : (a.x + b2.x);
                }
                g_ps[blk][tid] = s;
            } else if (tid == CAP_DIM) {
                float zt = 0.f;
#pragma unroll
                for (int w2 = 0; w2 < NWARP; w2++) zt += sm_z[w2];
                g_pz[blk] = zt * (1.f / 16.f);   // each pair's e counted 16x
            }
        }

        // ---- arrive ----
        __threadfence();
        __syncthreads();
        if (tid == 0) {
            unsigned int prev = atomicAdd(&g_cnt[t], 1u);
            sm_last = (prev == RGRID - 1) ? 1u : 0u;
        }
        __syncthreads();

        if (sm_last) {
            // ---- combine (deterministic fixed-order reduction) ----
            __threadfence();
            float sr[2]; float sq = 0.f;
#pragma unroll
            for (int r = 0; r < 2; r++) {
                int idx = tid + r * RTPB;        // idx = n2*32 + d  (2048 total)
                int n2 = idx >> 5, d = idx & 31;
                float num = g_ps[2 * n2][d] + g_ps[2 * n2 + 1][d];
                float Z = (t == 0) ? (float)IN_CAPS : (g_pz[2 * n2] + g_pz[2 * n2 + 1]);
                float s = num / Z;
                sr[r] = s; sq += s * s;
            }
#pragma unroll
            for (int o = 16; o > 0; o >>= 1) sq += __shfl_xor_sync(0xffffffffu, sq, o);
            if (lane == 0) sm_red[wid] = sq;
            __syncthreads();
            if (tid == 0) {
                float tt = 0.f;
#pragma unroll
                for (int k = 0; k < NWARP; k++) tt += sm_red[k];
                sm_scale = tt / (1.0f + tt) / (sqrtf(tt) + EPS);
            }
            __syncthreads();
            const float scale = sm_scale;
#pragma unroll
            for (int r = 0; r < 2; r++) {
                int idx = tid + r * RTPB;
                float v = sr[r] * scale;
                if (t == 0)      g_v[idx] = v;       // overwrite: replay-safe init
                else if (t == 1) g_v[idx] += v;      // cumulative for iter 2
                else             out[idx] = v;       // final output
            }
            __threadfence();
            __syncthreads();
            if (tid == 0) {
                if (t < 2) {
                    atomicExch(&g_flag[t], 1u);      // release
                } else {
                    g_cnt[0] = 0u; g_cnt[1] = 0u; g_cnt[2] = 0u;   // replay reset
                    g_flag[0] = 0u; g_flag[1] = 0u;
                }
            }
        } else {
            if (t == 2) return;                      // partials written; done
            if (tid == 0) {
                while (atomicAdd(&g_flag[t], 0u) == 0u) __nanosleep(64);
            }
            __syncthreads();
            __threadfence();
        }
    }
}

// ---------------------------------------------------------------------------
extern "C" void kernel_launch(void* const* d_in, const int* in_sizes, int n_in,
                              void* d_out, int out_size) {
    const float* x = (const float*)d_in[0];
    const float* W = (const float*)d_in[1];
    if (in_sizes[0] > in_sizes[1]) { const float* t = x; x = W; W = t; }
    float* out = (float*)d_out;

    const int pairs = N_CAPS * IN_CAPS;          // 262144
    uhat_kernel<<<pairs / 8, 256>>>(W, x);       // proven >=7.2 TB/s config
    route_kernel<<<RGRID, RTPB>>>(out);          // 3 fused routing iterations
}

// round 12
// speedup vs baseline: 1.0096x; 1.0096x over previous
#include <cuda_runtime.h>
#include <cuda_fp16.h>
#include <math.h>

#define N_CAPS 64
#define IN_CAPS 4096
#define CAP_DIM 32
#define IN_DIM 16
#define EPS 1e-7f

#define RGRID 128                // routing blocks; co-resident (1 block/SM)
#define RTPB 1024
#define NWARP 32
#define PPB (N_CAPS * IN_CAPS / RGRID)  // 2048 pairs per routing block
#define PPW (PPB / NWARP)               // 64 pairs per warp
#define SMEM_U_BYTES (PPB * CAP_DIM * 2)  // 131072 B of fp16 u per block

// globals (allocation-free rule)
__device__ __half g_u16[(size_t)N_CAPS * IN_CAPS * CAP_DIM];  // 16.75 MB fp16 u
__device__ float g_ps[RGRID][CAP_DIM];    // per-block partial S
__device__ float g_pz[RGRID];             // per-block partial Z
__device__ float g_v[N_CAPS * CAP_DIM];   // cumulative v
__device__ unsigned int g_cnt[3] = {0u, 0u, 0u};
__device__ unsigned int g_flag[2] = {0u, 0u};

// ---------------------------------------------------------------------------
// u[n,i,d] = sum_k W[n,i,d,k] * x[i,k]
// Standalone HBM-streaming config (~6.9-7.2 TB/s measured): one warp per
// (n,i) pair, lane = d, 256 tpb, huge grid, no smem, compiler-scheduled.
// Output fp16 (word k of pair = dims 2k,2k+1 — the routing layout).
// ---------------------------------------------------------------------------
__global__ __launch_bounds__(256) void uhat_kernel(const float* __restrict__ W,
                                                   const float* __restrict__ x) {
    int w = blockIdx.x * 8 + (threadIdx.x >> 5);   // global pair index
    int lane = threadIdx.x & 31;                   // d
    int i = w & (IN_CAPS - 1);

    const float4* xp = reinterpret_cast<const float4*>(x + (size_t)i * IN_DIM);
    float4 x0 = xp[0], x1 = xp[1], x2 = xp[2], x3 = xp[3];  // warp-uniform bcast

    const float4* wp = reinterpret_cast<const float4*>(
        W + ((size_t)w * CAP_DIM + lane) * IN_DIM);
    float4 w0 = wp[0], w1 = wp[1], w2 = wp[2], w3 = wp[3];

    float acc = w0.x * x0.x + w0.y * x0.y + w0.z * x0.z + w0.w * x0.w;
    acc      += w1.x * x1.x + w1.y * x1.y + w1.z * x1.z + w1.w * x1.w;
    acc      += w2.x * x2.x + w2.y * x2.y + w2.z * x2.z + w2.w * x2.w;
    acc      += w3.x * x3.x + w3.y * x3.y + w3.z * x3.z + w3.w * x3.w;

    g_u16[(size_t)w * CAP_DIM + lane] = __float2half_rn(acc);
}

// ---------------------------------------------------------------------------
// Persistent routing kernel. Iter 0 (e==1) doubles as the global->SMEM copy
// of this block's u slice; iters 1-2 run entirely out of SMEM (29-cyc LDS vs
// 234-cyc L2). Software grid barrier + last-block combine each iteration.
// 16-lane groups: lane k owns dims 2k,2k+1.
// ---------------------------------------------------------------------------
__global__ void __launch_bounds__(RTPB, 1)
route_kernel(float* __restrict__ out)
{
    extern __shared__ unsigned int u_sm[];        // [pair*16 + k] = dims 2k,2k+1
    const int tid  = threadIdx.x;
    const int wid  = tid >> 5;
    const int lane = tid & 31;
    const int blk  = blockIdx.x;
    const int n    = blk >> 1;

    const unsigned int* __restrict__ u32 =
        reinterpret_cast<const unsigned int*>(g_u16) + (size_t)blk * PPB * 16;

    __shared__ float2 sm_B[NWARP][CAP_DIM];
    __shared__ float  sm_z[NWARP];
    __shared__ float  sm_red[NWARP];
    __shared__ float  sm_scale;
    __shared__ unsigned int sm_last;

    for (int t = 0; t < 3; t++) {
        // ---- scan: partial S (and Z for t>0) over this block's pairs ----
        {
            const int l16 = lane & 15;
            float2 vv = make_float2(0.f, 0.f);
            if (t > 0)
                vv = *reinterpret_cast<const float2*>(&g_v[n * CAP_DIM + 2 * l16]);
            float ax = 0.f, ay = 0.f, z = 0.f;
            const int pbase = wid * PPW + (lane >> 4);

            if (t == 0) {
                // e == 1 pass doubles as global -> SMEM staging of u
#pragma unroll 4
                for (int s2 = 0; s2 < PPW / 2; s2++) {
                    const int off = (pbase + 2 * s2) * 16 + l16;
                    unsigned int wrd = u32[off];
                    u_sm[off] = wrd;
                    __half2 h = *reinterpret_cast<__half2*>(&wrd);
                    float2 uu = __half22float2(h);
                    ax += uu.x; ay += uu.y;
                }
            } else {
#pragma unroll 4
                for (int s2 = 0; s2 < PPW / 2; s2++) {
                    unsigned int wrd = u_sm[(pbase + 2 * s2) * 16 + l16];
                    __half2 h = *reinterpret_cast<__half2*>(&wrd);
                    float2 uu = __half22float2(h);
                    float dt = uu.x * vv.x + uu.y * vv.y;
                    dt += __shfl_xor_sync(0xffffffffu, dt, 1);
                    dt += __shfl_xor_sync(0xffffffffu, dt, 2);
                    dt += __shfl_xor_sync(0xffffffffu, dt, 4);
                    dt += __shfl_xor_sync(0xffffffffu, dt, 8);   // 16-lane dot
                    float e = __expf(dt);
                    ax += e * uu.x; ay += e * uu.y; z += e;
                }
            }
            sm_B[wid][lane] = make_float2(ax, ay);
            if (t > 0) {
#pragma unroll
                for (int o = 16; o > 0; o >>= 1) z += __shfl_xor_sync(0xffffffffu, z, o);
                if (lane == 0) sm_z[wid] = z;
            }
            __syncthreads();
            if (tid < CAP_DIM) {
                const int k = tid >> 1, j = tid & 1;
                float s = 0.f;
#pragma unroll
                for (int w2 = 0; w2 < NWARP; w2++) {
                    float2 a  = sm_B[w2][k];
                    float2 b2 = sm_B[w2][k + 16];
                    s += j ? (a.y + b2.y) : (a.x + b2.x);
                }
                g_ps[blk][tid] = s;
            } else if (tid == CAP_DIM && t > 0) {
                float zt = 0.f;
#pragma unroll
                for (int w2 = 0; w2 < NWARP; w2++) zt += sm_z[w2];
                g_pz[blk] = zt * (1.f / 16.f);   // each pair's e counted 16x
            }
        }

        // ---- arrive ----
        __threadfence();
        __syncthreads();
        if (tid == 0) {
            unsigned int prev = atomicAdd(&g_cnt[t], 1u);
            sm_last = (prev == RGRID - 1) ? 1u : 0u;
        }
        __syncthreads();

        if (sm_last) {
            // ---- combine (deterministic fixed-order reduction) ----
            __threadfence();
            float sr[2]; float sq = 0.f;
#pragma unroll
            for (int r = 0; r < 2; r++) {
                int idx = tid + r * RTPB;        // idx = n2*32 + d  (2048 total)
                int n2 = idx >> 5, d = idx & 31;
                float num = g_ps[2 * n2][d] + g_ps[2 * n2 + 1][d];
                float Z = (t == 0) ? (float)IN_CAPS : (g_pz[2 * n2] + g_pz[2 * n2 + 1]);
                float s = num / Z;
                sr[r] = s; sq += s * s;
            }
#pragma unroll
            for (int o = 16; o > 0; o >>= 1) sq += __shfl_xor_sync(0xffffffffu, sq, o);
            if (lane == 0) sm_red[wid] = sq;
            __syncthreads();
            if (tid == 0) {
                float tt = 0.f;
#pragma unroll
                for (int k = 0; k < NWARP; k++) tt += sm_red[k];
                sm_scale = tt / (1.0f + tt) / (sqrtf(tt) + EPS);
            }
            __syncthreads();
            const float scale = sm_scale;
#pragma unroll
            for (int r = 0; r < 2; r++) {
                int idx = tid + r * RTPB;
                float v = sr[r] * scale;
                if (t == 0)      g_v[idx] = v;       // overwrite: replay-safe init
                else if (t == 1) g_v[idx] += v;      // cumulative for iter 2
                else             out[idx] = v;       // final output
            }
            __threadfence();
            __syncthreads();
            if (tid == 0) {
                if (t < 2) {
                    atomicExch(&g_flag[t], 1u);      // release
                } else {
                    g_cnt[0] = 0u; g_cnt[1] = 0u; g_cnt[2] = 0u;   // replay reset
                    g_flag[0] = 0u; g_flag[1] = 0u;
                }
            }
        } else {
            if (t == 2) return;                      // partials written; done
            if (tid == 0) {
                while (atomicAdd(&g_flag[t], 0u) == 0u) __nanosleep(64);
            }
            __syncthreads();
            __threadfence();
        }
    }
}

// ---------------------------------------------------------------------------
extern "C" void kernel_launch(void* const* d_in, const int* in_sizes, int n_in,
                              void* d_out, int out_size) {
    const float* x = (const float*)d_in[0];
    const float* W = (const float*)d_in[1];
    if (in_sizes[0] > in_sizes[1]) { const float* t = x; x = W; W = t; }
    float* out = (float*)d_out;

    const int pairs = N_CAPS * IN_CAPS;          // 262144
    uhat_kernel<<<pairs / 8, 256>>>(W, x);       // HBM-streaming u = W.x

    cudaFuncSetAttribute(route_kernel,
                         cudaFuncAttributeMaxDynamicSharedMemorySize, SMEM_U_BYTES);
    route_kernel<<<RGRID, RTPB, SMEM_U_BYTES>>>(out);
}